// round 1
// baseline (speedup 1.0000x reference)
#include <cuda_runtime.h>
#include <cstdint>
#include <math.h>

// Problem constants
#define TOK   4096      // B*S tokens
#define RNUM  8
#define DDIM  768
#define FDIM  3072
#define VDIM  2048

// ---------------- device scratch (no allocations allowed) ----------------
__device__ __align__(256) float g_H[(size_t)TOK * FDIM];       // relu(x@W1+b1), permuted rows
__device__ __align__(256) float g_logits[(size_t)TOK * VDIM];  // h@W2+b2, permuted rows
__device__ int g_perm[TOK];
__device__ int g_seg_start[RNUM + 1];

// ---------------- helpers ----------------
__device__ __forceinline__ uint32_t smem_u32(const void* p) {
    return (uint32_t)__cvta_generic_to_shared(p);
}
__device__ __forceinline__ void cp16(uint32_t s, const void* g) {
    asm volatile("cp.async.cg.shared.global [%0], [%1], 16;\n" :: "r"(s), "l"(g));
}
__device__ __forceinline__ uint32_t f2tf32(float x) {
    uint32_t o;
    asm("cvt.rna.tf32.f32 %0, %1;\n" : "=r"(o) : "f"(x));
    return o;
}
__device__ __forceinline__ void mma_tf32(float* c, const uint32_t* a, const uint32_t* b) {
    asm volatile(
        "mma.sync.aligned.m16n8k8.row.col.f32.tf32.tf32.f32 "
        "{%0,%1,%2,%3},{%4,%5,%6,%7},{%8,%9},{%0,%1,%2,%3};\n"
        : "+f"(c[0]), "+f"(c[1]), "+f"(c[2]), "+f"(c[3])
        : "r"(a[0]), "r"(a[1]), "r"(a[2]), "r"(a[3]), "r"(b[0]), "r"(b[1]));
}

// ---------------- kernel 1: bucket tokens by route ----------------
__global__ void bucket_kernel(const int* __restrict__ route_ids) {
    __shared__ int s_cnt[RNUM];
    __shared__ int s_cur[RNUM];
    const int t = threadIdx.x;
    if (t < RNUM) s_cnt[t] = 0;
    __syncthreads();
    for (int i = t; i < TOK; i += blockDim.x)
        atomicAdd(&s_cnt[route_ids[i]], 1);
    __syncthreads();
    if (t == 0) {
        int off = 0;
        for (int r = 0; r < RNUM; r++) {
            g_seg_start[r] = off;
            s_cur[r] = off;
            off += s_cnt[r];
        }
        g_seg_start[RNUM] = off;  // == TOK
    }
    __syncthreads();
    for (int i = t; i < TOK; i += blockDim.x) {
        int r = route_ids[i];
        int pos = atomicAdd(&s_cur[r], 1);
        g_perm[pos] = i;
    }
}

// ---------------- GEMM (shared by both phases) ----------------
// PHASE1: A = e_two gathered via perm, K=768,  N=3072, C=g_H (relu + b1)
// PHASE2: A = g_H (contiguous, permuted), K=3072, N=2048, C=g_logits (+ b2)
// CTA tile 128x128, BK=16, double-buffered cp.async, 8 warps of 64x32 warp tiles.
template <bool PHASE1>
__global__ __launch_bounds__(256)
void gemm_kernel(const float* __restrict__ Aext,
                 const float* __restrict__ Bbase,
                 const float* __restrict__ biasBase) {
    constexpr int K = PHASE1 ? DDIM : FDIM;
    constexpr int N = PHASE1 ? FDIM : VDIM;
    constexpr int NK = K / 16;

    const int r = blockIdx.z;
    const int seg0 = g_seg_start[r];
    const int cnt  = g_seg_start[r + 1] - seg0;
    const int m0   = blockIdx.y * 128;
    if (m0 >= cnt) return;
    const int n0 = blockIdx.x * 128;

    const float* Abase = PHASE1 ? Aext : (const float*)g_H;
    float*       Cbase = PHASE1 ? (float*)g_H : (float*)g_logits;
    const float* B     = Bbase + (size_t)r * K * N;
    const float* bias  = biasBase + (size_t)r * N;

    __shared__ float sA[2][128][20];   // 16 used + 4 pad (stride 20 -> conflict-free frags)
    __shared__ float sB[2][16][132];   // 128 used + 4 pad
    __shared__ int   sRow[128];        // global A-row per tile row

    const int tid = threadIdx.x;
    if (tid < 128) {
        int mr = m0 + tid;
        if (mr >= cnt) mr = cnt - 1;   // clamp (results discarded by store guard)
        sRow[tid] = PHASE1 ? g_perm[seg0 + mr] : (seg0 + mr);
    }
    __syncthreads();

    auto load_tile = [&](int kt, int buf) {
        const int k0 = kt * 16;
        // A tile: 128 rows x 16 floats = 512 x 16B chunks, 2/thread
        #pragma unroll
        for (int i = 0; i < 2; i++) {
            int idx = tid + i * 256;
            int row = idx >> 2;
            int ch  = idx & 3;
            const float* g = Abase + (size_t)sRow[row] * K + k0 + ch * 4;
            cp16(smem_u32(&sA[buf][row][ch * 4]), g);
        }
        // B tile: 16 rows x 128 floats = 512 x 16B chunks, 2/thread
        #pragma unroll
        for (int i = 0; i < 2; i++) {
            int idx = tid + i * 256;
            int row = idx >> 5;
            int ch  = idx & 31;
            const float* g = B + (size_t)(k0 + row) * N + n0 + ch * 4;
            cp16(smem_u32(&sB[buf][row][ch * 4]), g);
        }
        asm volatile("cp.async.commit_group;\n");
    };

    float acc[4][4][4];
    #pragma unroll
    for (int mt = 0; mt < 4; mt++)
        #pragma unroll
        for (int nt = 0; nt < 4; nt++)
            #pragma unroll
            for (int j = 0; j < 4; j++) acc[mt][nt][j] = 0.f;

    const int warp = tid >> 5;
    const int lane = tid & 31;
    const int wm = warp & 1;    // 2 warp-rows of 64
    const int wn = warp >> 1;   // 4 warp-cols of 32
    const int lg = lane >> 2;   // groupID 0..7
    const int lt = lane & 3;    // threadID-in-group 0..3

    load_tile(0, 0);

    for (int kt = 0; kt < NK; kt++) {
        const int buf = kt & 1;
        if (kt + 1 < NK) {
            load_tile(kt + 1, buf ^ 1);
            asm volatile("cp.async.wait_group 1;\n");
        } else {
            asm volatile("cp.async.wait_group 0;\n");
        }
        __syncthreads();

        #pragma unroll
        for (int ks = 0; ks < 2; ks++) {
            uint32_t afr[4][4];
            uint32_t bfr[4][2];
            const int c = ks * 8 + lt;
            #pragma unroll
            for (int mt = 0; mt < 4; mt++) {
                const int rb = wm * 64 + mt * 16 + lg;
                afr[mt][0] = f2tf32(sA[buf][rb    ][c]);
                afr[mt][1] = f2tf32(sA[buf][rb + 8][c]);
                afr[mt][2] = f2tf32(sA[buf][rb    ][c + 4]);
                afr[mt][3] = f2tf32(sA[buf][rb + 8][c + 4]);
            }
            const int rbb = ks * 8 + lt;
            #pragma unroll
            for (int nt = 0; nt < 4; nt++) {
                const int cc = wn * 32 + nt * 8 + lg;
                bfr[nt][0] = f2tf32(sB[buf][rbb    ][cc]);
                bfr[nt][1] = f2tf32(sB[buf][rbb + 4][cc]);
            }
            #pragma unroll
            for (int mt = 0; mt < 4; mt++)
                #pragma unroll
                for (int nt = 0; nt < 4; nt++)
                    mma_tf32(acc[mt][nt], afr[mt], bfr[nt]);
        }
        __syncthreads();
    }

    // epilogue: bias (+relu for phase1), guarded float2 stores
    #pragma unroll
    for (int mt = 0; mt < 4; mt++) {
        #pragma unroll
        for (int half = 0; half < 2; half++) {
            const int rowl = wm * 64 + mt * 16 + lg + half * 8;
            const int mrow = m0 + rowl;
            if (mrow < cnt) {
                float* crow = Cbase + (size_t)(seg0 + mrow) * N;
                #pragma unroll
                for (int nt = 0; nt < 4; nt++) {
                    const int col = n0 + wn * 32 + nt * 8 + lt * 2;
                    float v0 = acc[mt][nt][half * 2 + 0] + bias[col];
                    float v1 = acc[mt][nt][half * 2 + 1] + bias[col + 1];
                    if (PHASE1) {
                        v0 = fmaxf(v0, 0.f);
                        v1 = fmaxf(v1, 0.f);
                    }
                    float2 v = make_float2(v0, v1);
                    *reinterpret_cast<float2*>(crow + col) = v;
                }
            }
        }
    }
}

// ---------------- kernel 4: softmax + scatter to real token rows ----------------
__global__ __launch_bounds__(256)
void softmax_kernel(float* __restrict__ out) {
    const int i   = blockIdx.x;        // permuted row
    const int tok = g_perm[i];
    const float* lrow = g_logits + (size_t)i * VDIM;
    float*       orow = out + (size_t)tok * VDIM;
    const int tid = threadIdx.x;

    float v[8];
    float mx = -1e30f;
    #pragma unroll
    for (int j = 0; j < 8; j++) {
        v[j] = lrow[tid + 256 * j];
        mx = fmaxf(mx, v[j]);
    }
    #pragma unroll
    for (int o = 16; o; o >>= 1) mx = fmaxf(mx, __shfl_xor_sync(0xffffffffu, mx, o));

    __shared__ float sred[8];
    const int w = tid >> 5;
    if ((tid & 31) == 0) sred[w] = mx;
    __syncthreads();
    float bmx = sred[0];
    #pragma unroll
    for (int j = 1; j < 8; j++) bmx = fmaxf(bmx, sred[j]);

    float s = 0.f;
    #pragma unroll
    for (int j = 0; j < 8; j++) {
        v[j] = expf(v[j] - bmx);
        s += v[j];
    }
    #pragma unroll
    for (int o = 16; o; o >>= 1) s += __shfl_xor_sync(0xffffffffu, s, o);
    __syncthreads();
    if ((tid & 31) == 0) sred[w] = s;
    __syncthreads();
    float tot = 0.f;
    #pragma unroll
    for (int j = 0; j < 8; j++) tot += sred[j];
    const float inv = 1.f / tot;
    #pragma unroll
    for (int j = 0; j < 8; j++) orow[tid + 256 * j] = v[j] * inv;
}

// ---------------- launch ----------------
extern "C" void kernel_launch(void* const* d_in, const int* in_sizes, int n_in,
                              void* d_out, int out_size) {
    const float* e_two     = (const float*)d_in[0];   // [4,1024,768]
    const int*   route_ids = (const int*)d_in[1];     // [4,1024]
    const float* W1        = (const float*)d_in[2];   // [8,768,3072]
    const float* b1        = (const float*)d_in[3];   // [8,3072]
    const float* W2        = (const float*)d_in[4];   // [8,3072,2048]
    const float* b2        = (const float*)d_in[5];   // [8,2048]
    float*       out       = (float*)d_out;           // [4,1024,2048]

    bucket_kernel<<<1, 512>>>(route_ids);

    dim3 g1(FDIM / 128, TOK / 128, RNUM);   // (24, 32, 8), most CTAs early-exit
    gemm_kernel<true><<<g1, 256>>>(e_two, W1, b1);

    dim3 g2(VDIM / 128, TOK / 128, RNUM);   // (16, 32, 8)
    gemm_kernel<false><<<g2, 256>>>(nullptr, W2, b2);

    softmax_kernel<<<TOK, 256>>>(out);
}

// round 3
// speedup vs baseline: 1.1251x; 1.1251x over previous
#include <cuda_runtime.h>
#include <cstdint>
#include <math.h>

// ---------------- problem constants ----------------
#define TOK   4096
#define RNUM  8
#define DDIM  768
#define FDIM  3072
#define VDIM  2048

// ---------------- device scratch ----------------
__device__ __align__(256) float g_Aperm[(size_t)TOK * DDIM];   // gathered + tf32-rounded activations
__device__ __align__(256) float g_H[(size_t)TOK * FDIM];       // relu(x@W1+b1), permuted rows, tf32-rounded
__device__ __align__(256) float g_logits[(size_t)TOK * VDIM];  // h@W2+b2, permuted rows
__device__ int g_perm[TOK];
__device__ int g_seg_start[RNUM + 1];

// ---------------- helpers ----------------
__device__ __forceinline__ uint32_t smem_u32(const void* p) {
    return (uint32_t)__cvta_generic_to_shared(p);
}
__device__ __forceinline__ void cp16(uint32_t s, const void* g) {
    asm volatile("cp.async.cg.shared.global [%0], [%1], 16;\n" :: "r"(s), "l"(g));
}
__device__ __forceinline__ uint32_t f2tf32(float x) {
    uint32_t o;
    asm("cvt.rna.tf32.f32 %0, %1;\n" : "=r"(o) : "f"(x));
    return o;
}
__device__ __forceinline__ float round_tf32(float x) {
    return __uint_as_float(f2tf32(x));
}
__device__ __forceinline__ void ldsm4(uint32_t* r, uint32_t addr) {
    asm volatile("ldmatrix.sync.aligned.m8n8.x4.shared.b16 {%0,%1,%2,%3}, [%4];\n"
                 : "=r"(r[0]), "=r"(r[1]), "=r"(r[2]), "=r"(r[3]) : "r"(addr));
}
__device__ __forceinline__ void mma_tf32(float* c, const uint32_t* a, const uint32_t* b) {
    asm volatile(
        "mma.sync.aligned.m16n8k8.row.col.f32.tf32.tf32.f32 "
        "{%0,%1,%2,%3},{%4,%5,%6,%7},{%8,%9},{%0,%1,%2,%3};\n"
        : "+f"(c[0]), "+f"(c[1]), "+f"(c[2]), "+f"(c[3])
        : "r"(a[0]), "r"(a[1]), "r"(a[2]), "r"(a[3]), "r"(b[0]), "r"(b[1]));
}

// ---------------- kernel 1: bucket tokens by route ----------------
__global__ void bucket_kernel(const int* __restrict__ route_ids) {
    __shared__ int s_cnt[RNUM];
    __shared__ int s_cur[RNUM];
    const int t = threadIdx.x;
    if (t < RNUM) s_cnt[t] = 0;
    __syncthreads();
    for (int i = t; i < TOK; i += blockDim.x)
        atomicAdd(&s_cnt[route_ids[i]], 1);
    __syncthreads();
    if (t == 0) {
        int off = 0;
        for (int r = 0; r < RNUM; r++) {
            g_seg_start[r] = off;
            s_cur[r] = off;
            off += s_cnt[r];
        }
        g_seg_start[RNUM] = off;
    }
    __syncthreads();
    for (int i = t; i < TOK; i += blockDim.x) {
        int r = route_ids[i];
        int pos = atomicAdd(&s_cur[r], 1);
        g_perm[pos] = i;
    }
}

// ---------------- kernel 2: gather A rows by perm, round to tf32 ----------------
__global__ __launch_bounds__(192)
void gather_kernel(const float* __restrict__ e_two) {
    const int row = blockIdx.x;
    const int tok = g_perm[row];
    const float4* src = reinterpret_cast<const float4*>(e_two + (size_t)tok * DDIM);
    float4* dst = reinterpret_cast<float4*>(g_Aperm + (size_t)row * DDIM);
    float4 v = src[threadIdx.x];
    v.x = round_tf32(v.x); v.y = round_tf32(v.y);
    v.z = round_tf32(v.z); v.w = round_tf32(v.w);
    dst[threadIdx.x] = v;
}

// ---------------- tf32 GEMM (legacy mma.sync + ldmatrix A path) ----------------
// C[128x128 tile] = A[128 x K] @ B[K x 128] (+bias, optional relu+round)
// A rows contiguous (permuted space). BK=32, 2-stage cp.async double buffer.
// 8 warps: 2 (m) x 4 (n), warp tile 64x32, mma m16n8k8 tf32.
// A fragments via ldmatrix.x4 (A pre-rounded to tf32 -> no cvt needed, exact).
// B fragments via scalar LDS + cvt.rna.tf32.
static constexpr int BK = 32;
static constexpr int SA_STRIDE = 36;    // 32 + 4 pad floats (rows step 4 banks -> conflict-free)
static constexpr int SB_STRIDE = 132;   // 128 + 4 pad
static constexpr int SA_FLOATS = 128 * SA_STRIDE;         // per stage
static constexpr int SB_FLOATS = BK * SB_STRIDE;          // per stage
static constexpr int SMEM_FLOATS = 2 * (SA_FLOATS + SB_FLOATS);
static constexpr int SMEM_BYTES  = SMEM_FLOATS * 4;       // 69,504 B

template <int KTOT, int NTOT, bool RELU>
__global__ void __launch_bounds__(256, 2)
gemm_legacy(const float* __restrict__ Abase,
            const float* __restrict__ Bbase,
            const float* __restrict__ biasBase,
            float* __restrict__ Cbase) {
    constexpr int NK = KTOT / BK;

    extern __shared__ float smem[];
    float* sA = smem;                       // [2][128][SA_STRIDE]
    float* sB = smem + 2 * SA_FLOATS;       // [2][BK][SB_STRIDE]

    const int r    = blockIdx.z;
    const int seg0 = g_seg_start[r];
    const int cnt  = g_seg_start[r + 1] - seg0;
    const int m0   = blockIdx.y * 128;
    if (m0 >= cnt) return;
    const int n0 = blockIdx.x * 128;

    const float* B    = Bbase + (size_t)r * KTOT * NTOT;
    const float* bias = biasBase + (size_t)r * NTOT;

    const int tid  = threadIdx.x;
    const int warp = tid >> 5;
    const int lane = tid & 31;
    const int wm = warp & 1;    // 2 warp-rows of 64
    const int wn = warp >> 1;   // 4 warp-cols of 32
    const int lg = lane >> 2;
    const int lt = lane & 3;

    // cp.async tile loader: A 128x32 floats (1024 16B-chunks), B 32x128 (1024 chunks)
    auto load_tile = [&](int kt, int buf) {
        const int k0 = kt * BK;
        float* dA = sA + buf * SA_FLOATS;
        float* dB = sB + buf * SB_FLOATS;
        #pragma unroll
        for (int i = 0; i < 4; i++) {
            int idx = tid + i * 256;
            int row = idx >> 3;          // 0..127
            int ch  = idx & 7;           // 0..7 (16B chunks of 32 floats)
            int grow = seg0 + m0 + row;
            if (grow > TOK - 1) grow = TOK - 1;   // clamp: stores are guarded
            cp16(smem_u32(dA + row * SA_STRIDE + ch * 4),
                 Abase + (size_t)grow * KTOT + k0 + ch * 4);
        }
        #pragma unroll
        for (int i = 0; i < 4; i++) {
            int idx = tid + i * 256;
            int row = idx >> 5;          // 0..31
            int ch  = idx & 31;          // 0..31
            cp16(smem_u32(dB + row * SB_STRIDE + ch * 4),
                 B + (size_t)(k0 + row) * NTOT + n0 + ch * 4);
        }
        asm volatile("cp.async.commit_group;\n");
    };

    float acc[4][4][4];
    #pragma unroll
    for (int mt = 0; mt < 4; mt++)
        #pragma unroll
        for (int nt = 0; nt < 4; nt++)
            #pragma unroll
            for (int j = 0; j < 4; j++) acc[mt][nt][j] = 0.f;

    // per-lane ldmatrix base offset (within an A stage buffer), in bytes:
    // row = wm*64 + (lane&7) + 8*((lane>>3)&1), col(float) = 4*((lane>>4)&1)
    const int a_row = wm * 64 + (lane & 7) + (((lane >> 3) & 1) << 3);
    const int a_col = ((lane >> 4) & 1) << 2;
    const uint32_t aAddrBase = smem_u32(sA + a_row * SA_STRIDE + a_col);

    load_tile(0, 0);

    for (int kt = 0; kt < NK; kt++) {
        const int buf = kt & 1;
        if (kt + 1 < NK) {
            load_tile(kt + 1, buf ^ 1);
            asm volatile("cp.async.wait_group 1;\n");
        } else {
            asm volatile("cp.async.wait_group 0;\n");
        }
        __syncthreads();

        const uint32_t aBuf = aAddrBase + buf * (SA_FLOATS * 4);
        const float*   bBuf = sB + buf * SB_FLOATS;

        #pragma unroll
        for (int ks = 0; ks < 4; ks++) {            // 4 k-steps of 8
            uint32_t afr[4][4];
            #pragma unroll
            for (int mt = 0; mt < 4; mt++)
                ldsm4(afr[mt], aBuf + mt * (16 * SA_STRIDE * 4) + ks * 32);

            uint32_t bfr[4][2];
            const int kb = ks * 8 + lt;
            #pragma unroll
            for (int nt = 0; nt < 4; nt++) {
                const int cc = wn * 32 + nt * 8 + lg;
                bfr[nt][0] = f2tf32(bBuf[kb * SB_STRIDE + cc]);
                bfr[nt][1] = f2tf32(bBuf[(kb + 4) * SB_STRIDE + cc]);
            }
            #pragma unroll
            for (int mt = 0; mt < 4; mt++)
                #pragma unroll
                for (int nt = 0; nt < 4; nt++)
                    mma_tf32(acc[mt][nt], afr[mt], bfr[nt]);
        }
        __syncthreads();
    }

    // epilogue: bias (+relu+tf32-round for phase1), guarded float2 stores
    #pragma unroll
    for (int mt = 0; mt < 4; mt++) {
        #pragma unroll
        for (int half = 0; half < 2; half++) {
            const int rowl = wm * 64 + mt * 16 + lg + half * 8;
            const int mrow = m0 + rowl;
            if (mrow < cnt) {
                float* crow = Cbase + (size_t)(seg0 + mrow) * NTOT;
                #pragma unroll
                for (int nt = 0; nt < 4; nt++) {
                    const int col = n0 + wn * 32 + nt * 8 + lt * 2;
                    float v0 = acc[mt][nt][half * 2 + 0] + bias[col];
                    float v1 = acc[mt][nt][half * 2 + 1] + bias[col + 1];
                    if (RELU) {
                        v0 = round_tf32(fmaxf(v0, 0.f));
                        v1 = round_tf32(fmaxf(v1, 0.f));
                    }
                    *reinterpret_cast<float2*>(crow + col) = make_float2(v0, v1);
                }
            }
        }
    }
}

// ---------------- kernel: softmax + scatter to real token rows ----------------
__global__ __launch_bounds__(256)
void softmax_kernel(float* __restrict__ out) {
    const int i   = blockIdx.x;
    const int tok = g_perm[i];
    const float* lrow = g_logits + (size_t)i * VDIM;
    float*       orow = out + (size_t)tok * VDIM;
    const int tid = threadIdx.x;

    float v[8];
    float mx = -1e30f;
    #pragma unroll
    for (int j = 0; j < 8; j++) {
        v[j] = lrow[tid + 256 * j];
        mx = fmaxf(mx, v[j]);
    }
    #pragma unroll
    for (int o = 16; o; o >>= 1) mx = fmaxf(mx, __shfl_xor_sync(0xffffffffu, mx, o));

    __shared__ float sred[8];
    const int w = tid >> 5;
    if ((tid & 31) == 0) sred[w] = mx;
    __syncthreads();
    float bmx = sred[0];
    #pragma unroll
    for (int j = 1; j < 8; j++) bmx = fmaxf(bmx, sred[j]);

    float s = 0.f;
    #pragma unroll
    for (int j = 0; j < 8; j++) {
        v[j] = expf(v[j] - bmx);
        s += v[j];
    }
    #pragma unroll
    for (int o = 16; o; o >>= 1) s += __shfl_xor_sync(0xffffffffu, s, o);
    __syncthreads();
    if ((tid & 31) == 0) sred[w] = s;
    __syncthreads();
    float tot = 0.f;
    #pragma unroll
    for (int j = 0; j < 8; j++) tot += sred[j];
    const float inv = 1.f / tot;
    #pragma unroll
    for (int j = 0; j < 8; j++) orow[tid + 256 * j] = v[j] * inv;
}

// ---------------- launch ----------------
extern "C" void kernel_launch(void* const* d_in, const int* in_sizes, int n_in,
                              void* d_out, int out_size) {
    const float* e_two     = (const float*)d_in[0];   // [4,1024,768]
    const int*   route_ids = (const int*)d_in[1];     // [4,1024]
    const float* W1        = (const float*)d_in[2];   // [8,768,3072]
    const float* b1        = (const float*)d_in[3];   // [8,3072]
    const float* W2        = (const float*)d_in[4];   // [8,3072,2048]
    const float* b2        = (const float*)d_in[5];   // [8,2048]
    float*       out       = (float*)d_out;           // [4,1024,2048]

    void *pA, *pH, *pL;
    cudaGetSymbolAddress(&pA, g_Aperm);
    cudaGetSymbolAddress(&pH, g_H);
    cudaGetSymbolAddress(&pL, g_logits);

    static bool attr_done = false;
    if (!attr_done) {
        cudaFuncSetAttribute(gemm_legacy<DDIM, FDIM, true>,
                             cudaFuncAttributeMaxDynamicSharedMemorySize, SMEM_BYTES);
        cudaFuncSetAttribute(gemm_legacy<FDIM, VDIM, false>,
                             cudaFuncAttributeMaxDynamicSharedMemorySize, SMEM_BYTES);
        attr_done = true;
    }

    bucket_kernel<<<1, 512>>>(route_ids);
    gather_kernel<<<TOK, 192>>>(e_two);

    dim3 g1(FDIM / 128, TOK / 128, RNUM);   // (24, 32, 8)
    gemm_legacy<DDIM, FDIM, true><<<g1, 256, SMEM_BYTES>>>(
        (const float*)pA, W1, b1, (float*)pH);

    dim3 g2(VDIM / 128, TOK / 128, RNUM);   // (16, 32, 8)
    gemm_legacy<FDIM, VDIM, false><<<g2, 256, SMEM_BYTES>>>(
        (const float*)pH, W2, b2, (float*)pL);

    softmax_kernel<<<TOK, 256>>>(out);
}